// round 9
// baseline (speedup 1.0000x reference)
#include <cuda_runtime.h>
#include <cstdint>
#include <cstddef>

#define TS 1024
#define BB 64
#define HH 1024
#define G4 4096

__device__ float g_xproj[(size_t)TS * BB * G4];
__device__ float g_h[2][BB * HH];
__device__ unsigned g_count = 0;
__device__ unsigned g_gen = 0;

typedef unsigned long long ull;
__device__ __forceinline__ ull pack2(float a, float b) {
    ull r; asm("mov.b64 %0, {%1, %2};" : "=l"(r) : "f"(a), "f"(b)); return r;
}
__device__ __forceinline__ void unpack2(ull p, float& a, float& b) {
    asm("mov.b64 {%0, %1}, %2;" : "=f"(a), "=f"(b) : "l"(p));
}
__device__ __forceinline__ ull ffma2(ull a, ull b, ull c) {
    ull d; asm("fma.rn.f32x2 %0, %1, %2, %3;" : "=l"(d) : "l"(a), "l"(b), "l"(c)); return d;
}
__device__ __forceinline__ float sigf(float x) { return 1.0f / (1.0f + __expf(-x)); }

// ===================== Kernel 1: x_proj GEMM (R5, proven) =====================
__global__ __launch_bounds__(256) void xproj_kernel(
    const float* __restrict__ X, const float* __restrict__ Wih,
    const float* __restrict__ bih, const float* __restrict__ bhh)
{
    __shared__ float As[2][16][128];
    __shared__ float Bs[2][16][128];
    const int tid = threadIdx.x;
    const int m0 = blockIdx.y * 128, n0 = blockIdx.x * 128;
    const int lm = tid & 127, lq = tid >> 7;
    const float* Xrow = X + (size_t)(m0 + lm) * HH;
    const float* Wrow = Wih + (size_t)(n0 + lm) * HH;
    const int tx = tid & 15, ty = tid >> 4;

    ull acc[8][4];
#pragma unroll
    for (int r = 0; r < 8; r++)
#pragma unroll
        for (int j = 0; j < 4; j++) acc[r][j] = 0ull;

    float4 xa[2], xb[2];
#pragma unroll
    for (int u = 0; u < 2; u++) {
        xa[u] = *(const float4*)&Xrow[(lq + 2 * u) * 4];
        xb[u] = *(const float4*)&Wrow[(lq + 2 * u) * 4];
    }
    for (int kt = 0; kt < 64; ++kt) {
        const int cur = kt & 1;
#pragma unroll
        for (int u = 0; u < 2; u++) {
            const int kq = (lq + 2 * u) * 4;
            As[cur][kq + 0][lm] = xa[u].x; As[cur][kq + 1][lm] = xa[u].y;
            As[cur][kq + 2][lm] = xa[u].z; As[cur][kq + 3][lm] = xa[u].w;
            Bs[cur][kq + 0][lm] = xb[u].x; Bs[cur][kq + 1][lm] = xb[u].y;
            Bs[cur][kq + 2][lm] = xb[u].z; Bs[cur][kq + 3][lm] = xb[u].w;
        }
        __syncthreads();
        if (kt < 63) {
            const int kb = (kt + 1) * 16;
#pragma unroll
            for (int u = 0; u < 2; u++) {
                xa[u] = *(const float4*)&Xrow[kb + (lq + 2 * u) * 4];
                xb[u] = *(const float4*)&Wrow[kb + (lq + 2 * u) * 4];
            }
        }
#pragma unroll
        for (int k = 0; k < 16; k++) {
            const float4 a0 = *(const float4*)&As[cur][k][ty * 8];
            const float4 a1 = *(const float4*)&As[cur][k][ty * 8 + 4];
            const ulonglong2 b0 = *(const ulonglong2*)&Bs[cur][k][tx * 8];
            const ulonglong2 b1 = *(const ulonglong2*)&Bs[cur][k][tx * 8 + 4];
            const ull bp[4] = { b0.x, b0.y, b1.x, b1.y };
            const float av[8] = { a0.x, a0.y, a0.z, a0.w, a1.x, a1.y, a1.z, a1.w };
#pragma unroll
            for (int r = 0; r < 8; r++) {
                const ull ar = pack2(av[r], av[r]);
#pragma unroll
                for (int j = 0; j < 4; j++) acc[r][j] = ffma2(ar, bp[j], acc[r][j]);
            }
        }
        __syncthreads();
    }
    float bias[8];
#pragma unroll
    for (int j = 0; j < 8; j++) bias[j] = bih[n0 + tx * 8 + j] + bhh[n0 + tx * 8 + j];
#pragma unroll
    for (int r = 0; r < 8; r++) {
        float c[8];
        unpack2(acc[r][0], c[0], c[1]); unpack2(acc[r][1], c[2], c[3]);
        unpack2(acc[r][2], c[4], c[5]); unpack2(acc[r][3], c[6], c[7]);
        float* Crow = g_xproj + (size_t)(m0 + ty * 8 + r) * G4 + n0 + tx * 8;
#pragma unroll
        for (int j = 0; j < 8; j++) Crow[j] = c[j] + bias[j];
    }
}

// ===================== grid barrier =====================
__device__ __forceinline__ void grid_barrier()
{
    __syncthreads();
    if (threadIdx.x == 0) {
        __threadfence();
        const unsigned gen = *(volatile unsigned*)&g_gen;
        atomicAdd(&g_count, 1u);
        if (blockIdx.x == 0) {
            while (*(volatile unsigned*)&g_count != gridDim.x) { __nanosleep(64); }
            g_count = 0;
            __threadfence();
            atomicAdd(&g_gen, 1u);
        } else {
            while (*(volatile unsigned*)&g_gen == gen) { __nanosleep(64); }
        }
        __threadfence();
    }
    __syncthreads();
}

// ===================== Kernel 2: persistent recurrence, 512 threads ==========
// 128 CTAs x 512 threads. CTA bid owns h-cols [8*bid, 8*bid+8) => 32 gate cols.
// Thread (cg=tid&3, kc=tid>>2): gate cg, cols j0..j0+8, k-chunk [kc*8, kc*8+8).
// W slice = 64 floats/thread in registers. Per batch: 32 ffma2 ->
// 7-shuffle butterfly -> 16-slice cross-warp smem sum (warps 0-7) ->
// quad allgather -> cell on gate-0 lane.
__global__ __launch_bounds__(512, 1) void lstm_rec_kernel(
    const float* __restrict__ Whh, const float* __restrict__ h0,
    const float* __restrict__ c0, float* __restrict__ out, int out_size)
{
    __shared__ float red[2][8 * 16 * 32];   // [buf][bl][warp][lane]

    const int tid = threadIdx.x;
    const int j0 = blockIdx.x * 8;
    const int cg = tid & 3;
    const int kc = tid >> 2;
    const int kb = kc * 8;
    const int lane = tid & 31;
    const int wid = tid >> 5;               // 0..15
    const int jl = (lane >> 2) & 7;
    const bool front = (wid < 8);
    const bool writer = front && (cg == 0);

    // ---- W_hh slice into registers (once): 8 k-floats x 4 col-pairs ----
    ull wreg[8][4];
#pragma unroll
    for (int p = 0; p < 4; p++) {
        const float* r0 = Whh + (size_t)(cg * HH + j0 + 2 * p) * HH + kb;
        const float* r1 = r0 + HH;
        const float4 a0 = *(const float4*)&r0[0];
        const float4 a1 = *(const float4*)&r0[4];
        const float4 b0 = *(const float4*)&r1[0];
        const float4 b1 = *(const float4*)&r1[4];
        const float w0[8] = { a0.x, a0.y, a0.z, a0.w, a1.x, a1.y, a1.z, a1.w };
        const float w1[8] = { b0.x, b0.y, b0.z, b0.w, b1.x, b1.y, b1.z, b1.w };
#pragma unroll
        for (int k = 0; k < 8; k++) wreg[k][p] = pack2(w0[k], w1[k]);
    }

    // ---- c state in registers (meaningful on writer lanes, warps 0-7) ----
    float c_reg[8];
#pragma unroll
    for (int grp = 0; grp < 8; grp++)
        c_reg[grp] = front ? c0[(size_t)(grp * 8 + wid) * HH + j0 + jl] : 0.f;

    const int hT = TS * BB * HH;
    const bool wr_tail = out_size >= hT + 2 * BB * HH;

    for (int t = 0; t < TS; ++t) {
        const float* __restrict__ hsrc = (t == 0) ? h0 : g_h[(t + 1) & 1];
        float* __restrict__ hdst = g_h[t & 1];
        const float* __restrict__ xpt = g_xproj + (size_t)t * BB * G4;

        float4 hbuf[2][2];
#pragma unroll
        for (int u = 0; u < 2; u++) {
            const float4* hp = (const float4*)(hsrc + (size_t)u * HH + kb);
            hbuf[u][0] = __ldcg(hp);
            hbuf[u][1] = __ldcg(hp + 1);
        }

        for (int grp = 0; grp < 8; ++grp) {
            const float xpv = front
                ? __ldcs(&xpt[(size_t)(grp * 8 + wid) * G4 + cg * HH + j0 + jl])
                : 0.f;
            float* redb = red[grp & 1];

#pragma unroll
            for (int bl = 0; bl < 8; bl++) {
                float4 hc[2];
                hc[0] = hbuf[bl & 1][0];
                hc[1] = hbuf[bl & 1][1];
                const int pb = grp * 8 + bl + 2;
                if (pb < BB) {
                    const float4* hp = (const float4*)(hsrc + (size_t)pb * HH + kb);
                    hbuf[bl & 1][0] = __ldcg(hp);
                    hbuf[bl & 1][1] = __ldcg(hp + 1);
                }

                ull acc[4] = {0ull, 0ull, 0ull, 0ull};
#pragma unroll
                for (int q = 0; q < 2; q++) {
                    ull av[4];
                    av[0] = pack2(hc[q].x, hc[q].x);
                    av[1] = pack2(hc[q].y, hc[q].y);
                    av[2] = pack2(hc[q].z, hc[q].z);
                    av[3] = pack2(hc[q].w, hc[q].w);
#pragma unroll
                    for (int kk = 0; kk < 4; kk++)
#pragma unroll
                        for (int p = 0; p < 4; p++)
                            acc[p] = ffma2(av[kk], wreg[q * 4 + kk][p], acc[p]);
                }

                // ---- value-halving butterfly over 8 kc-lanes ----
                float v[8];
                unpack2(acc[0], v[0], v[1]); unpack2(acc[1], v[2], v[3]);
                unpack2(acc[2], v[4], v[5]); unpack2(acc[3], v[6], v[7]);

                float u4[4];
                {
                    const bool bit = (lane & 16) != 0;
#pragma unroll
                    for (int i = 0; i < 4; i++) {
                        const float send = bit ? v[i] : v[i + 4];
                        const float recv = __shfl_xor_sync(0xffffffffu, send, 16);
                        u4[i] = (bit ? v[i + 4] : v[i]) + recv;
                    }
                }
                float u2a[2];
                {
                    const bool bit = (lane & 8) != 0;
#pragma unroll
                    for (int i = 0; i < 2; i++) {
                        const float send = bit ? u4[i] : u4[i + 2];
                        const float recv = __shfl_xor_sync(0xffffffffu, send, 8);
                        u2a[i] = (bit ? u4[i + 2] : u4[i]) + recv;
                    }
                }
                float rsum;
                {
                    const bool bit = (lane & 4) != 0;
                    const float send = bit ? u2a[0] : u2a[1];
                    const float recv = __shfl_xor_sync(0xffffffffu, send, 4);
                    rsum = (bit ? u2a[1] : u2a[0]) + recv;
                }
                redb[(bl * 16 + wid) * 32 + lane] = rsum;
            }
            __syncthreads();

            // ---- cross-warp sum: warp w (<8) handles batch grp*8+w ----
            if (front) {
                float gsum = xpv;
#pragma unroll
                for (int s = 0; s < 16; s++)
                    gsum += redb[(wid * 16 + s) * 32 + lane];

                const float act = (cg == 2) ? tanhf(gsum) : sigf(gsum);
                const float a1 = __shfl_xor_sync(0xffffffffu, act, 1);
                const float a2 = __shfl_xor_sync(0xffffffffu, act, 2);
                const float a3 = __shfl_xor_sync(0xffffffffu, a1, 2);

                if (cg == 0) {
                    // on cg==0 lane: act=i, a1=f, a2=g, a3=o
                    const float cn = fmaf(a1, c_reg[grp], act * a2);
                    c_reg[grp] = cn;
                    const float hv = a3 * tanhf(cn);
                    const int b = grp * 8 + wid;
                    hdst[(size_t)b * HH + j0 + jl] = hv;
                    out[((size_t)t * BB + b) * HH + j0 + jl] = hv;
                }
            }
        }
        grid_barrier();
    }

    if (wr_tail && writer) {
        const float* hfin = g_h[(TS - 1) & 1];
#pragma unroll
        for (int grp = 0; grp < 8; grp++) {
            const int b = grp * 8 + wid;
            out[hT + (size_t)b * HH + j0 + jl] = hfin[(size_t)b * HH + j0 + jl];
            out[hT + BB * HH + (size_t)b * HH + j0 + jl] = c_reg[grp];
        }
    }
}

extern "C" void kernel_launch(void* const* d_in, const int* in_sizes, int n_in,
                              void* d_out, int out_size)
{
    const float* x   = (const float*)d_in[0];
    const float* Wih = (const float*)d_in[1];
    const float* Whh = (const float*)d_in[2];
    const float* bih = (const float*)d_in[3];
    const float* bhh = (const float*)d_in[4];
    const float* h0  = (const float*)d_in[5];
    const float* c0  = (const float*)d_in[6];
    float* out = (float*)d_out;

    dim3 g1(G4 / 128, (TS * BB) / 128);
    xproj_kernel<<<g1, 256>>>(x, Wih, bih, bhh);
    lstm_rec_kernel<<<128, 512>>>(Whh, h0, c0, out, out_size);
}

// round 11
// speedup vs baseline: 1.4932x; 1.4932x over previous
#include <cuda_runtime.h>
#include <cuda_bf16.h>
#include <cstdint>
#include <cstddef>

#define TS 1024
#define BB 64
#define HH 1024
#define G4 4096
#define K3 3072

__device__ float g_xproj[(size_t)TS * BB * G4];
__device__ float g_h[2][BB * HH];
__device__ unsigned g_count = 0;
__device__ unsigned g_gen = 0;
__device__ __align__(256) __nv_bfloat16 g_xc[(size_t)TS * BB * K3];  // [row][hi|hi|lo]
__device__ __align__(256) __nv_bfloat16 g_wc[(size_t)G4 * K3];       // [row][hi|lo|hi]

typedef unsigned long long ull;
__device__ __forceinline__ ull pack2(float a, float b) {
    ull r; asm("mov.b64 %0, {%1, %2};" : "=l"(r) : "f"(a), "f"(b)); return r;
}
__device__ __forceinline__ void unpack2(ull p, float& a, float& b) {
    asm("mov.b64 {%0, %1}, %2;" : "=f"(a), "=f"(b) : "l"(p));
}
__device__ __forceinline__ ull ffma2(ull a, ull b, ull c) {
    ull d; asm("fma.rn.f32x2 %0, %1, %2, %3;" : "=l"(d) : "l"(a), "l"(b), "l"(c)); return d;
}
__device__ __forceinline__ float sigf(float x) { return 1.0f / (1.0f + __expf(-x)); }

__device__ __forceinline__ uint32_t su32(const void* p) {
    uint32_t a;
    asm("{ .reg .u64 t; cvta.to.shared.u64 t, %1; cvt.u32.u64 %0, t; }" : "=r"(a) : "l"(p));
    return a;
}

#define CPA16(dst, src) asm volatile("cp.async.cg.shared.global [%0], [%1], 16;" :: "r"(dst), "l"(src))
#define CPA_COMMIT() asm volatile("cp.async.commit_group;" ::: "memory")
#define CPA_WAIT1() asm volatile("cp.async.wait_group 1;" ::: "memory")

#define LDSM4(r, addr) asm volatile( \
    "ldmatrix.sync.aligned.m8n8.x4.shared.b16 {%0,%1,%2,%3}, [%4];" \
    : "=r"((r)[0]), "=r"((r)[1]), "=r"((r)[2]), "=r"((r)[3]) : "r"(addr))

#define MMA16816(d, a, b0, b1) asm volatile( \
    "mma.sync.aligned.m16n8k16.row.col.f32.bf16.bf16.f32 " \
    "{%0,%1,%2,%3}, {%4,%5,%6,%7}, {%8,%9}, {%0,%1,%2,%3};" \
    : "+f"((d)[0]), "+f"((d)[1]), "+f"((d)[2]), "+f"((d)[3]) \
    : "r"((a)[0]), "r"((a)[1]), "r"((a)[2]), "r"((a)[3]), "r"(b0), "r"(b1))

// ======== conversion: fp32 -> MISMATCHED concat (computes hi.hi+hi.lo+lo.hi) ==
// X row: [hi | hi | lo],  W row: [hi | lo | hi]
__global__ __launch_bounds__(256) void cvt_x_kernel(const float* __restrict__ src) {
    const size_t i = (size_t)blockIdx.x * 256 + threadIdx.x;
    const float4 v = ((const float4*)src)[i];
    const size_t e = i * 4;
    __nv_bfloat16* d = g_xc + (e >> 10) * K3 + (e & 1023);
    const float f[4] = { v.x, v.y, v.z, v.w };
    __nv_bfloat16 h[4], l[4];
#pragma unroll
    for (int j = 0; j < 4; j++) {
        h[j] = __float2bfloat16(f[j]);
        l[j] = __float2bfloat16(f[j] - __bfloat162float(h[j]));
    }
    *(__nv_bfloat162*)(d)        = __nv_bfloat162(h[0], h[1]);
    *(__nv_bfloat162*)(d + 2)    = __nv_bfloat162(h[2], h[3]);
    *(__nv_bfloat162*)(d + 1024) = __nv_bfloat162(h[0], h[1]);
    *(__nv_bfloat162*)(d + 1026) = __nv_bfloat162(h[2], h[3]);
    *(__nv_bfloat162*)(d + 2048) = __nv_bfloat162(l[0], l[1]);
    *(__nv_bfloat162*)(d + 2050) = __nv_bfloat162(l[2], l[3]);
}
__global__ __launch_bounds__(256) void cvt_w_kernel(const float* __restrict__ src) {
    const size_t i = (size_t)blockIdx.x * 256 + threadIdx.x;
    const float4 v = ((const float4*)src)[i];
    const size_t e = i * 4;
    __nv_bfloat16* d = g_wc + (e >> 10) * K3 + (e & 1023);
    const float f[4] = { v.x, v.y, v.z, v.w };
    __nv_bfloat16 h[4], l[4];
#pragma unroll
    for (int j = 0; j < 4; j++) {
        h[j] = __float2bfloat16(f[j]);
        l[j] = __float2bfloat16(f[j] - __bfloat162float(h[j]));
    }
    *(__nv_bfloat162*)(d)        = __nv_bfloat162(h[0], h[1]);
    *(__nv_bfloat162*)(d + 2)    = __nv_bfloat162(h[2], h[3]);
    *(__nv_bfloat162*)(d + 1024) = __nv_bfloat162(l[0], l[1]);
    *(__nv_bfloat162*)(d + 1026) = __nv_bfloat162(l[2], l[3]);
    *(__nv_bfloat162*)(d + 2048) = __nv_bfloat162(h[0], h[1]);
    *(__nv_bfloat162*)(d + 2050) = __nv_bfloat162(h[2], h[3]);
}

// ===================== Kernel 1: x_proj GEMM via mma.sync bf16 (R8 verbatim) ==
__global__ __launch_bounds__(256) void xproj_mma_kernel(
    const float* __restrict__ bih, const float* __restrict__ bhh)
{
    __shared__ __align__(16) char As[2 * 128 * 80];
    __shared__ __align__(16) char Bs[2 * 128 * 80];
    __shared__ float bias_sm[128];

    const int tid = threadIdx.x, wid = tid >> 5, lane = tid & 31;
    const int n0 = blockIdx.x * 128, m0 = blockIdx.y * 128;
    const int wm = wid & 3, wn = wid >> 2;
    const uint32_t suA = su32(As), suB = su32(Bs);
    const __nv_bfloat16* Xc = g_xc;
    const __nv_bfloat16* Wc = g_wc;

    if (tid < 128) bias_sm[tid] = bih[n0 + tid] + bhh[n0 + tid];

    float c[2][8][4];
#pragma unroll
    for (int mf = 0; mf < 2; mf++)
#pragma unroll
        for (int nf = 0; nf < 8; nf++)
#pragma unroll
            for (int q = 0; q < 4; q++) c[mf][nf][q] = 0.f;

    auto load_stage = [&](int kt, int buf) {
#pragma unroll
        for (int u = 0; u < 2; u++) {
            const int idx = tid + 256 * u;
            const int row = idx >> 2, c4 = idx & 3;
            CPA16(suA + buf * 10240 + row * 80 + c4 * 16,
                  Xc + (size_t)(m0 + row) * K3 + kt * 32 + c4 * 8);
            CPA16(suB + buf * 10240 + row * 80 + c4 * 16,
                  Wc + (size_t)(n0 + row) * K3 + kt * 32 + c4 * 8);
        }
    };

    load_stage(0, 0); CPA_COMMIT();
    load_stage(1, 1); CPA_COMMIT();

    const int lrow = lane & 15;
    const int lkof = (lane >> 4) << 4;

    const int NKT = K3 / 32;   // 96
    for (int kt = 0; kt < NKT; ++kt) {
        const int buf = kt & 1;
        CPA_WAIT1();
        __syncthreads();
        const uint32_t Ab = suA + buf * 10240;
        const uint32_t Bb = suB + buf * 10240;
#pragma unroll
        for (int s = 0; s < 2; s++) {
            const int kby = s * 32 + lkof;
            uint32_t a0[4], a1[4];
            LDSM4(a0, Ab + (wm * 32 + lrow) * 80 + kby);
            LDSM4(a1, Ab + (wm * 32 + 16 + lrow) * 80 + kby);
            uint32_t bf[4][4];
#pragma unroll
            for (int n4 = 0; n4 < 4; n4++)
                LDSM4(bf[n4], Bb + (wn * 64 + n4 * 16 + lrow) * 80 + kby);
#pragma unroll
            for (int n4 = 0; n4 < 4; n4++) {
                MMA16816(c[0][n4 * 2],     a0, bf[n4][0], bf[n4][2]);
                MMA16816(c[0][n4 * 2 + 1], a0, bf[n4][1], bf[n4][3]);
                MMA16816(c[1][n4 * 2],     a1, bf[n4][0], bf[n4][2]);
                MMA16816(c[1][n4 * 2 + 1], a1, bf[n4][1], bf[n4][3]);
            }
        }
        __syncthreads();
        if (kt + 2 < NKT) load_stage(kt + 2, buf);
        CPA_COMMIT();
    }

    const int rbase = m0 + wm * 32 + (lane >> 2);
    const int cloc = wn * 64 + (lane & 3) * 2;
#pragma unroll
    for (int mf = 0; mf < 2; mf++) {
#pragma unroll
        for (int nf = 0; nf < 8; nf++) {
            const int col = cloc + nf * 8;
            const float b0 = bias_sm[col], b1 = bias_sm[col + 1];
            float* p0 = g_xproj + (size_t)(rbase + mf * 16) * G4 + n0 + col;
            float* p1 = p0 + 8 * G4;
            *(float2*)p0 = make_float2(c[mf][nf][0] + b0, c[mf][nf][1] + b1);
            *(float2*)p1 = make_float2(c[mf][nf][2] + b0, c[mf][nf][3] + b1);
        }
    }
}

// ===================== grid barrier =====================
__device__ __forceinline__ void grid_barrier()
{
    __syncthreads();
    if (threadIdx.x == 0) {
        __threadfence();
        const unsigned gen = *(volatile unsigned*)&g_gen;
        atomicAdd(&g_count, 1u);
        if (blockIdx.x == 0) {
            while (*(volatile unsigned*)&g_count != gridDim.x) { __nanosleep(64); }
            g_count = 0;
            __threadfence();
            atomicAdd(&g_gen, 1u);
        } else {
            while (*(volatile unsigned*)&g_gen == gen) { __nanosleep(64); }
        }
        __threadfence();
    }
    __syncthreads();
}

// ===================== Kernel 2: persistent recurrence (R5, proven) ==========
__global__ __launch_bounds__(256, 1) void lstm_rec_kernel(
    const float* __restrict__ Whh, const float* __restrict__ h0,
    const float* __restrict__ c0, float* __restrict__ out, int out_size)
{
    __shared__ float red[2][8 * 8 * 32];

    const int tid = threadIdx.x;
    const int j0 = blockIdx.x * 8;
    const int cg = tid & 3;
    const int kc = tid >> 2;
    const int kb = kc * 16;
    const int lane = tid & 31;
    const int wid = tid >> 5;
    const int jl = (lane >> 2) & 7;
    const bool writer = (cg == 0);

    ull wreg[16][4];
#pragma unroll
    for (int p = 0; p < 4; p++) {
        const float* r0 = Whh + (size_t)(cg * HH + j0 + 2 * p) * HH + kb;
        const float* r1 = r0 + HH;
        float w0[16], w1[16];
#pragma unroll
        for (int q = 0; q < 4; q++) {
            const float4 a = *(const float4*)&r0[q * 4];
            const float4 b4 = *(const float4*)&r1[q * 4];
            w0[q*4+0] = a.x;  w0[q*4+1] = a.y;  w0[q*4+2] = a.z;  w0[q*4+3] = a.w;
            w1[q*4+0] = b4.x; w1[q*4+1] = b4.y; w1[q*4+2] = b4.z; w1[q*4+3] = b4.w;
        }
#pragma unroll
        for (int k = 0; k < 16; k++) wreg[k][p] = pack2(w0[k], w1[k]);
    }

    float c_reg[8];
#pragma unroll
    for (int grp = 0; grp < 8; grp++)
        c_reg[grp] = c0[(size_t)(grp * 8 + wid) * HH + j0 + jl];

    const int hT = TS * BB * HH;
    const bool wr_tail = out_size >= hT + 2 * BB * HH;

    for (int t = 0; t < TS; ++t) {
        const float* __restrict__ hsrc = (t == 0) ? h0 : g_h[(t + 1) & 1];
        float* __restrict__ hdst = g_h[t & 1];
        const float* __restrict__ xpt = g_xproj + (size_t)t * BB * G4;

        float4 hbuf[2][4];
#pragma unroll
        for (int u = 0; u < 2; u++) {
            const float4* hp = (const float4*)(hsrc + (size_t)u * HH + kb);
#pragma unroll
            for (int q = 0; q < 4; q++) hbuf[u][q] = __ldcg(hp + q);
        }

        for (int grp = 0; grp < 8; ++grp) {
            const float xpv =
                __ldcs(&xpt[(size_t)(grp * 8 + wid) * G4 + cg * HH + j0 + jl]);
            float* redb = red[grp & 1];

#pragma unroll
            for (int bl = 0; bl < 8; bl++) {
                float4 hc[4];
#pragma unroll
                for (int q = 0; q < 4; q++) hc[q] = hbuf[bl & 1][q];
                const int pb = grp * 8 + bl + 2;
                if (pb < BB) {
                    const float4* hp = (const float4*)(hsrc + (size_t)pb * HH + kb);
#pragma unroll
                    for (int q = 0; q < 4; q++) hbuf[bl & 1][q] = __ldcg(hp + q);
                }

                ull acc[4] = {0ull, 0ull, 0ull, 0ull};
#pragma unroll
                for (int q = 0; q < 4; q++) {
                    ull av[4];
                    av[0] = pack2(hc[q].x, hc[q].x);
                    av[1] = pack2(hc[q].y, hc[q].y);
                    av[2] = pack2(hc[q].z, hc[q].z);
                    av[3] = pack2(hc[q].w, hc[q].w);
#pragma unroll
                    for (int kk = 0; kk < 4; kk++)
#pragma unroll
                        for (int p = 0; p < 4; p++)
                            acc[p] = ffma2(av[kk], wreg[q * 4 + kk][p], acc[p]);
                }

                float v[8];
                unpack2(acc[0], v[0], v[1]); unpack2(acc[1], v[2], v[3]);
                unpack2(acc[2], v[4], v[5]); unpack2(acc[3], v[6], v[7]);

                float u4[4];
                {
                    const bool bit = (lane & 16) != 0;
#pragma unroll
                    for (int i = 0; i < 4; i++) {
                        const float send = bit ? v[i] : v[i + 4];
                        const float recv = __shfl_xor_sync(0xffffffffu, send, 16);
                        u4[i] = (bit ? v[i + 4] : v[i]) + recv;
                    }
                }
                float u2a[2];
                {
                    const bool bit = (lane & 8) != 0;
#pragma unroll
                    for (int i = 0; i < 2; i++) {
                        const float send = bit ? u4[i] : u4[i + 2];
                        const float recv = __shfl_xor_sync(0xffffffffu, send, 8);
                        u2a[i] = (bit ? u4[i + 2] : u4[i]) + recv;
                    }
                }
                float rsum;
                {
                    const bool bit = (lane & 4) != 0;
                    const float send = bit ? u2a[0] : u2a[1];
                    const float recv = __shfl_xor_sync(0xffffffffu, send, 4);
                    rsum = (bit ? u2a[1] : u2a[0]) + recv;
                }
                redb[(bl * 8 + wid) * 32 + lane] = rsum;
            }
            __syncthreads();

            float gsum = xpv;
#pragma unroll
            for (int w = 0; w < 8; w++)
                gsum += redb[(wid * 8 + w) * 32 + lane];

            const float act = (cg == 2) ? tanhf(gsum) : sigf(gsum);
            const float a1 = __shfl_xor_sync(0xffffffffu, act, 1);
            const float a2 = __shfl_xor_sync(0xffffffffu, act, 2);
            const float a3 = __shfl_xor_sync(0xffffffffu, a1, 2);

            if (writer) {
                const float cn = fmaf(a1, c_reg[grp], act * a2);
                c_reg[grp] = cn;
                const float hv = a3 * tanhf(cn);
                const int b = grp * 8 + wid;
                hdst[(size_t)b * HH + j0 + jl] = hv;
                out[((size_t)t * BB + b) * HH + j0 + jl] = hv;
            }
        }
        grid_barrier();
    }

    if (wr_tail && writer) {
        const float* hfin = g_h[(TS - 1) & 1];
#pragma unroll
        for (int grp = 0; grp < 8; grp++) {
            const int b = grp * 8 + wid;
            out[hT + (size_t)b * HH + j0 + jl] = hfin[(size_t)b * HH + j0 + jl];
            out[hT + BB * HH + (size_t)b * HH + j0 + jl] = c_reg[grp];
        }
    }
}

extern "C" void kernel_launch(void* const* d_in, const int* in_sizes, int n_in,
                              void* d_out, int out_size)
{
    const float* x   = (const float*)d_in[0];
    const float* Wih = (const float*)d_in[1];
    const float* Whh = (const float*)d_in[2];
    const float* bih = (const float*)d_in[3];
    const float* bhh = (const float*)d_in[4];
    const float* h0  = (const float*)d_in[5];
    const float* c0  = (const float*)d_in[6];
    float* out = (float*)d_out;

    cvt_x_kernel<<<(TS * BB * HH / 4) / 256, 256>>>(x);
    cvt_w_kernel<<<(G4 * HH / 4) / 256, 256>>>(Wih);
    dim3 g1(G4 / 128, (TS * BB) / 128);
    xproj_mma_kernel<<<g1, 256>>>(bih, bhh);
    lstm_rec_kernel<<<128, 256>>>(Whh, h0, c0, out, out_size);
}

// round 12
// speedup vs baseline: 2.2032x; 1.4755x over previous
#include <cuda_runtime.h>
#include <cuda_bf16.h>
#include <cstdint>
#include <cstddef>

#define TS 1024
#define BB 64
#define HH 1024
#define G4 4096
#define K3 3072

__device__ float g_xproj[(size_t)TS * BB * G4];
__device__ unsigned g_count = 0;
__device__ unsigned g_gen = 0;
__device__ __align__(256) __nv_bfloat16 g_xc[(size_t)TS * BB * K3];  // [row][hi|hi|lo]
__device__ __align__(256) __nv_bfloat16 g_wc[(size_t)G4 * K3];       // [row][hi|lo|hi]
__device__ __align__(256) __nv_bfloat16 g_hh[3][2][BB * HH];         // [buf][hi/lo][b*HH+j]

__device__ __forceinline__ float sigf(float x) { return 1.0f / (1.0f + __expf(-x)); }

__device__ __forceinline__ uint32_t su32(const void* p) {
    uint32_t a;
    asm("{ .reg .u64 t; cvta.to.shared.u64 t, %1; cvt.u32.u64 %0, t; }" : "=r"(a) : "l"(p));
    return a;
}

#define CPA16(dst, src) asm volatile("cp.async.cg.shared.global [%0], [%1], 16;" :: "r"(dst), "l"(src))
#define CPA_COMMIT() asm volatile("cp.async.commit_group;" ::: "memory")
#define CPA_WAIT1() asm volatile("cp.async.wait_group 1;" ::: "memory")

#define LDSM4(r, addr) asm volatile( \
    "ldmatrix.sync.aligned.m8n8.x4.shared.b16 {%0,%1,%2,%3}, [%4];" \
    : "=r"((r)[0]), "=r"((r)[1]), "=r"((r)[2]), "=r"((r)[3]) : "r"(addr))

#define MMA16816(d, a, b0, b1) asm volatile( \
    "mma.sync.aligned.m16n8k16.row.col.f32.bf16.bf16.f32 " \
    "{%0,%1,%2,%3}, {%4,%5,%6,%7}, {%8,%9}, {%0,%1,%2,%3};" \
    : "+f"((d)[0]), "+f"((d)[1]), "+f"((d)[2]), "+f"((d)[3]) \
    : "r"((a)[0]), "r"((a)[1]), "r"((a)[2]), "r"((a)[3]), "r"(b0), "r"(b1))

// ======== conversion: fp32 -> MISMATCHED concat (R10, proven) ========
__global__ __launch_bounds__(256) void cvt_x_kernel(const float* __restrict__ src) {
    const size_t i = (size_t)blockIdx.x * 256 + threadIdx.x;
    const float4 v = ((const float4*)src)[i];
    const size_t e = i * 4;
    __nv_bfloat16* d = g_xc + (e >> 10) * K3 + (e & 1023);
    const float f[4] = { v.x, v.y, v.z, v.w };
    __nv_bfloat16 h[4], l[4];
#pragma unroll
    for (int j = 0; j < 4; j++) {
        h[j] = __float2bfloat16(f[j]);
        l[j] = __float2bfloat16(f[j] - __bfloat162float(h[j]));
    }
    *(__nv_bfloat162*)(d)        = __nv_bfloat162(h[0], h[1]);
    *(__nv_bfloat162*)(d + 2)    = __nv_bfloat162(h[2], h[3]);
    *(__nv_bfloat162*)(d + 1024) = __nv_bfloat162(h[0], h[1]);
    *(__nv_bfloat162*)(d + 1026) = __nv_bfloat162(h[2], h[3]);
    *(__nv_bfloat162*)(d + 2048) = __nv_bfloat162(l[0], l[1]);
    *(__nv_bfloat162*)(d + 2050) = __nv_bfloat162(l[2], l[3]);
}
__global__ __launch_bounds__(256) void cvt_w_kernel(const float* __restrict__ src) {
    const size_t i = (size_t)blockIdx.x * 256 + threadIdx.x;
    const float4 v = ((const float4*)src)[i];
    const size_t e = i * 4;
    __nv_bfloat16* d = g_wc + (e >> 10) * K3 + (e & 1023);
    const float f[4] = { v.x, v.y, v.z, v.w };
    __nv_bfloat16 h[4], l[4];
#pragma unroll
    for (int j = 0; j < 4; j++) {
        h[j] = __float2bfloat16(f[j]);
        l[j] = __float2bfloat16(f[j] - __bfloat162float(h[j]));
    }
    *(__nv_bfloat162*)(d)        = __nv_bfloat162(h[0], h[1]);
    *(__nv_bfloat162*)(d + 2)    = __nv_bfloat162(h[2], h[3]);
    *(__nv_bfloat162*)(d + 1024) = __nv_bfloat162(l[0], l[1]);
    *(__nv_bfloat162*)(d + 1026) = __nv_bfloat162(l[2], l[3]);
    *(__nv_bfloat162*)(d + 2048) = __nv_bfloat162(h[0], h[1]);
    *(__nv_bfloat162*)(d + 2050) = __nv_bfloat162(h[2], h[3]);
}

// ===================== Kernel 1: x_proj GEMM via mma.sync (R10, proven) ======
__global__ __launch_bounds__(256) void xproj_mma_kernel(
    const float* __restrict__ bih, const float* __restrict__ bhh)
{
    __shared__ __align__(16) char As[2 * 128 * 80];
    __shared__ __align__(16) char Bs[2 * 128 * 80];
    __shared__ float bias_sm[128];

    const int tid = threadIdx.x, wid = tid >> 5, lane = tid & 31;
    const int n0 = blockIdx.x * 128, m0 = blockIdx.y * 128;
    const int wm = wid & 3, wn = wid >> 2;
    const uint32_t suA = su32(As), suB = su32(Bs);
    const __nv_bfloat16* Xc = g_xc;
    const __nv_bfloat16* Wc = g_wc;

    if (tid < 128) bias_sm[tid] = bih[n0 + tid] + bhh[n0 + tid];

    float c[2][8][4];
#pragma unroll
    for (int mf = 0; mf < 2; mf++)
#pragma unroll
        for (int nf = 0; nf < 8; nf++)
#pragma unroll
            for (int q = 0; q < 4; q++) c[mf][nf][q] = 0.f;

    auto load_stage = [&](int kt, int buf) {
#pragma unroll
        for (int u = 0; u < 2; u++) {
            const int idx = tid + 256 * u;
            const int row = idx >> 2, c4 = idx & 3;
            CPA16(suA + buf * 10240 + row * 80 + c4 * 16,
                  Xc + (size_t)(m0 + row) * K3 + kt * 32 + c4 * 8);
            CPA16(suB + buf * 10240 + row * 80 + c4 * 16,
                  Wc + (size_t)(n0 + row) * K3 + kt * 32 + c4 * 8);
        }
    };

    load_stage(0, 0); CPA_COMMIT();
    load_stage(1, 1); CPA_COMMIT();

    const int lrow = lane & 15;
    const int lkof = (lane >> 4) << 4;

    const int NKT = K3 / 32;
    for (int kt = 0; kt < NKT; ++kt) {
        const int buf = kt & 1;
        CPA_WAIT1();
        __syncthreads();
        const uint32_t Ab = suA + buf * 10240;
        const uint32_t Bb = suB + buf * 10240;
#pragma unroll
        for (int s = 0; s < 2; s++) {
            const int kby = s * 32 + lkof;
            uint32_t a0[4], a1[4];
            LDSM4(a0, Ab + (wm * 32 + lrow) * 80 + kby);
            LDSM4(a1, Ab + (wm * 32 + 16 + lrow) * 80 + kby);
            uint32_t bf[4][4];
#pragma unroll
            for (int n4 = 0; n4 < 4; n4++)
                LDSM4(bf[n4], Bb + (wn * 64 + n4 * 16 + lrow) * 80 + kby);
#pragma unroll
            for (int n4 = 0; n4 < 4; n4++) {
                MMA16816(c[0][n4 * 2],     a0, bf[n4][0], bf[n4][2]);
                MMA16816(c[0][n4 * 2 + 1], a0, bf[n4][1], bf[n4][3]);
                MMA16816(c[1][n4 * 2],     a1, bf[n4][0], bf[n4][2]);
                MMA16816(c[1][n4 * 2 + 1], a1, bf[n4][1], bf[n4][3]);
            }
        }
        __syncthreads();
        if (kt + 2 < NKT) load_stage(kt + 2, buf);
        CPA_COMMIT();
    }

    const int rbase = m0 + wm * 32 + (lane >> 2);
    const int cloc = wn * 64 + (lane & 3) * 2;
#pragma unroll
    for (int mf = 0; mf < 2; mf++) {
#pragma unroll
        for (int nf = 0; nf < 8; nf++) {
            const int col = cloc + nf * 8;
            const float b0 = bias_sm[col], b1 = bias_sm[col + 1];
            float* p0 = g_xproj + (size_t)(rbase + mf * 16) * G4 + n0 + col;
            float* p1 = p0 + 8 * G4;
            *(float2*)p0 = make_float2(c[mf][nf][0] + b0, c[mf][nf][1] + b1);
            *(float2*)p1 = make_float2(c[mf][nf][2] + b0, c[mf][nf][3] + b1);
        }
    }
}

// ===================== grid barrier =====================
__device__ __forceinline__ void grid_barrier()
{
    __syncthreads();
    if (threadIdx.x == 0) {
        __threadfence();
        const unsigned gen = *(volatile unsigned*)&g_gen;
        atomicAdd(&g_count, 1u);
        if (blockIdx.x == 0) {
            while (*(volatile unsigned*)&g_count != gridDim.x) { __nanosleep(64); }
            g_count = 0;
            __threadfence();
            atomicAdd(&g_gen, 1u);
        } else {
            while (*(volatile unsigned*)&g_gen == gen) { __nanosleep(64); }
        }
        __threadfence();
    }
    __syncthreads();
}

// ===================== Kernel 2: tensor-core persistent recurrence ===========
// 128 CTAs x 256 threads, 1/SM. CTA owns 32 gate cols (4 gates x 8 h-cols).
// W_hh slice hi/lo bf16 resident in smem. h streamed bf16 hi/lo (triple-
// buffered global). C[64x32] = h @ Wslice^T via mma.sync, 3 streams, 6 accum
// fragments. Cell fp32 in registers, c-state resident.
#define WROW 2064                  // 1024 bf16 + 8 pad (odd 16B multiple)
#define SM_WH 0
#define SM_WL 66048
#define SM_A  132096               // 2 bufs x (hi 5120 | lo 5120)
#define SM_C  152576               // 64 x 33 floats
#define ABUF  10240
#define SMT   161024

__global__ __launch_bounds__(256, 1) void lstm_rec_tc(
    const float* __restrict__ Whh, const float* __restrict__ h0,
    const float* __restrict__ c0, float* __restrict__ out, int out_size)
{
    extern __shared__ char sm[];
    const uint32_t smb = su32(sm);
    float* Csm = (float*)(sm + SM_C);

    const int tid = threadIdx.x, lane = tid & 31, wid = tid >> 5;
    const int j0 = blockIdx.x * 8;
    const int wm = wid & 3, wn = wid >> 2;
    const int lrow = lane & 15, lkof = (lane >> 4) << 4;
    const int b0_ = tid >> 3, jl = tid & 7;

    // ---- W_hh slice -> smem hi/lo (once) ----
    {
        const int n = tid >> 3, seg = tid & 7;
        const float* src = Whh + (size_t)((n >> 3) * HH + j0 + (n & 7)) * HH + seg * 128;
        __nv_bfloat16* dh = (__nv_bfloat16*)(sm + SM_WH + n * WROW) + seg * 128;
        __nv_bfloat16* dl = (__nv_bfloat16*)(sm + SM_WL + n * WROW) + seg * 128;
        for (int q = 0; q < 32; q++) {
            const float4 v = *(const float4*)&src[q * 4];
            const float f[4] = { v.x, v.y, v.z, v.w };
            __nv_bfloat16 h4[4], l4[4];
#pragma unroll
            for (int j = 0; j < 4; j++) {
                h4[j] = __float2bfloat16(f[j]);
                l4[j] = __float2bfloat16(f[j] - __bfloat162float(h4[j]));
            }
            *(__nv_bfloat162*)(dh + q * 4)     = __nv_bfloat162(h4[0], h4[1]);
            *(__nv_bfloat162*)(dh + q * 4 + 2) = __nv_bfloat162(h4[2], h4[3]);
            *(__nv_bfloat162*)(dl + q * 4)     = __nv_bfloat162(l4[0], l4[1]);
            *(__nv_bfloat162*)(dl + q * 4 + 2) = __nv_bfloat162(l4[2], l4[3]);
        }
    }
    // ---- h0 split -> g_hh[0] (each CTA converts a 512-elem slice) ----
    {
        const size_t e = ((size_t)blockIdx.x * 256 + tid) * 2;
        const float2 v = *(const float2*)&h0[e];
        const __nv_bfloat16 h0a = __float2bfloat16(v.x);
        const __nv_bfloat16 h0b = __float2bfloat16(v.y);
        *(__nv_bfloat162*)&g_hh[0][0][e] = __nv_bfloat162(h0a, h0b);
        *(__nv_bfloat162*)&g_hh[0][1][e] = __nv_bfloat162(
            __float2bfloat16(v.x - __bfloat162float(h0a)),
            __float2bfloat16(v.y - __bfloat162float(h0b)));
    }
    float c_reg[2], hlast[2] = {0.f, 0.f};
    c_reg[0] = c0[(size_t)b0_ * HH + j0 + jl];
    c_reg[1] = c0[(size_t)(b0_ + 32) * HH + j0 + jl];

    grid_barrier();

    const int hT = TS * BB * HH;

    for (int t = 0; t < TS; ++t) {
        const int rb = t % 3, wb = (t + 1) % 3;
        const char* Ah_g = (const char*)g_hh[rb][0];
        const char* Al_g = (const char*)g_hh[rb][1];

        // xp prefetch (consumed in epilogue)
        float xpv[2][4];
        {
            const float* xpt = g_xproj + (size_t)t * BB * G4;
#pragma unroll
            for (int q = 0; q < 2; q++)
#pragma unroll
                for (int g = 0; g < 4; g++)
                    xpv[q][g] = __ldcs(&xpt[(size_t)(b0_ + 32 * q) * G4 + g * HH + j0 + jl]);
        }

        float c[6][4];
#pragma unroll
        for (int i = 0; i < 6; i++)
#pragma unroll
            for (int q = 0; q < 4; q++) c[i][q] = 0.f;

        auto load_stage = [&](int kt, int bf) {
            const uint32_t dst = smb + SM_A + bf * ABUF + (tid >> 2) * 80 + (tid & 3) * 16;
            const size_t so = (size_t)(tid >> 2) * 2048 + kt * 64 + (tid & 3) * 16;
            CPA16(dst, Ah_g + so);
            CPA16(dst + 5120, Al_g + so);
        };
        load_stage(0, 0); CPA_COMMIT();
        load_stage(1, 1); CPA_COMMIT();

        const uint32_t Bhr = smb + SM_WH + (wn * 16 + lrow) * WROW;
        const uint32_t Blr = smb + SM_WL + (wn * 16 + lrow) * WROW;

        for (int kt = 0; kt < 32; ++kt) {
            CPA_WAIT1();
            __syncthreads();
            const uint32_t Ahs = smb + SM_A + (kt & 1) * ABUF + (wm * 16 + lrow) * 80;
            const uint32_t Als = Ahs + 5120;
#pragma unroll
            for (int s = 0; s < 2; s++) {
                const int kby = s * 32 + lkof;
                const int kwb = kt * 64 + kby;
                uint32_t ah[4], al[4], bh[4], bl[4];
                LDSM4(ah, Ahs + kby);
                LDSM4(al, Als + kby);
                LDSM4(bh, Bhr + kwb);
                LDSM4(bl, Blr + kwb);
                MMA16816(c[0], ah, bh[0], bh[2]);
                MMA16816(c[1], ah, bh[1], bh[3]);
                MMA16816(c[2], ah, bl[0], bl[2]);
                MMA16816(c[3], ah, bl[1], bl[3]);
                MMA16816(c[4], al, bh[0], bh[2]);
                MMA16816(c[5], al, bh[1], bh[3]);
            }
            __syncthreads();
            if (kt + 2 < 32) load_stage(kt + 2, kt & 1);
            CPA_COMMIT();
        }

        // ---- merge streams, fragments -> Csm ----
        {
            const int r0 = wm * 16 + (lane >> 2);
            const int cb = wn * 16 + (lane & 3) * 2;
#pragma unroll
            for (int nf = 0; nf < 2; nf++) {
                const float v0 = c[nf][0] + c[nf + 2][0] + c[nf + 4][0];
                const float v1 = c[nf][1] + c[nf + 2][1] + c[nf + 4][1];
                const float v2 = c[nf][2] + c[nf + 2][2] + c[nf + 4][2];
                const float v3 = c[nf][3] + c[nf + 2][3] + c[nf + 4][3];
                Csm[r0 * 33 + cb + nf * 8]           = v0;
                Csm[r0 * 33 + cb + nf * 8 + 1]       = v1;
                Csm[(r0 + 8) * 33 + cb + nf * 8]     = v2;
                Csm[(r0 + 8) * 33 + cb + nf * 8 + 1] = v3;
            }
        }
        __syncthreads();

        // ---- LSTM cell (fp32, c in registers) ----
#pragma unroll
        for (int q = 0; q < 2; q++) {
            const int b = b0_ + 32 * q;
            const float Gi = Csm[b * 33 + jl]      + xpv[q][0];
            const float Gf = Csm[b * 33 + 8 + jl]  + xpv[q][1];
            const float Gg = Csm[b * 33 + 16 + jl] + xpv[q][2];
            const float Go = Csm[b * 33 + 24 + jl] + xpv[q][3];
            const float iv = sigf(Gi), fv = sigf(Gf);
            const float gv = tanhf(Gg), ov = sigf(Go);
            const float cn = fmaf(fv, c_reg[q], iv * gv);
            c_reg[q] = cn;
            const float hv = ov * tanhf(cn);
            hlast[q] = hv;
            out[((size_t)t * BB + b) * HH + j0 + jl] = hv;
            const __nv_bfloat16 hh = __float2bfloat16(hv);
            g_hh[wb][0][b * HH + j0 + jl] = hh;
            g_hh[wb][1][b * HH + j0 + jl] =
                __float2bfloat16(hv - __bfloat162float(hh));
        }
        grid_barrier();
    }

    if (out_size >= hT + 2 * BB * HH) {
#pragma unroll
        for (int q = 0; q < 2; q++) {
            const int b = b0_ + 32 * q;
            out[hT + (size_t)b * HH + j0 + jl] = hlast[q];
            out[hT + BB * HH + (size_t)b * HH + j0 + jl] = c_reg[q];
        }
    }
}

extern "C" void kernel_launch(void* const* d_in, const int* in_sizes, int n_in,
                              void* d_out, int out_size)
{
    const float* x   = (const float*)d_in[0];
    const float* Wih = (const float*)d_in[1];
    const float* Whh = (const float*)d_in[2];
    const float* bih = (const float*)d_in[3];
    const float* bhh = (const float*)d_in[4];
    const float* h0  = (const float*)d_in[5];
    const float* c0  = (const float*)d_in[6];
    float* out = (float*)d_out;

    static bool attr_set = false;
    if (!attr_set) {
        cudaFuncSetAttribute(lstm_rec_tc,
                             cudaFuncAttributeMaxDynamicSharedMemorySize, SMT);
        attr_set = true;
    }

    cvt_x_kernel<<<(TS * BB * HH / 4) / 256, 256>>>(x);
    cvt_w_kernel<<<(G4 * HH / 4) / 256, 256>>>(Wih);
    dim3 g1(G4 / 128, (TS * BB) / 128);
    xproj_mma_kernel<<<g1, 256>>>(bih, bhh);
    lstm_rec_tc<<<128, 256, SMT>>>(Whh, h0, c0, out, out_size);
}

// round 13
// speedup vs baseline: 2.2595x; 1.0255x over previous
#include <cuda_runtime.h>
#include <cuda_bf16.h>
#include <cstdint>
#include <cstddef>

#define TS 1024
#define BB 64
#define HH 1024
#define G4 4096
#define K3 3072

__device__ float g_xproj[(size_t)TS * BB * G4];
__device__ unsigned g_count = 0;
__device__ unsigned g_gen = 0;
__device__ __align__(256) __nv_bfloat16 g_xc[(size_t)TS * BB * K3];  // [row][hi|hi|lo]
__device__ __align__(256) __nv_bfloat16 g_wc[(size_t)G4 * K3];       // [row][hi|lo|hi]
__device__ __align__(256) __nv_bfloat16 g_hh[3][2][BB * HH];         // [buf][hi/lo][b*HH+j]

__device__ __forceinline__ float sigf(float x) { return 1.0f / (1.0f + __expf(-x)); }

__device__ __forceinline__ uint32_t su32(const void* p) {
    uint32_t a;
    asm("{ .reg .u64 t; cvta.to.shared.u64 t, %1; cvt.u32.u64 %0, t; }" : "=r"(a) : "l"(p));
    return a;
}

#define CPA16(dst, src) asm volatile("cp.async.cg.shared.global [%0], [%1], 16;" :: "r"(dst), "l"(src))
#define CPA_COMMIT() asm volatile("cp.async.commit_group;" ::: "memory")
#define CPA_WAIT1() asm volatile("cp.async.wait_group 1;" ::: "memory")

#define LDSM4(r, addr) asm volatile( \
    "ldmatrix.sync.aligned.m8n8.x4.shared.b16 {%0,%1,%2,%3}, [%4];" \
    : "=r"((r)[0]), "=r"((r)[1]), "=r"((r)[2]), "=r"((r)[3]) : "r"(addr))

#define MMA16816(d, a, b0, b1) asm volatile( \
    "mma.sync.aligned.m16n8k16.row.col.f32.bf16.bf16.f32 " \
    "{%0,%1,%2,%3}, {%4,%5,%6,%7}, {%8,%9}, {%0,%1,%2,%3};" \
    : "+f"((d)[0]), "+f"((d)[1]), "+f"((d)[2]), "+f"((d)[3]) \
    : "r"((a)[0]), "r"((a)[1]), "r"((a)[2]), "r"((a)[3]), "r"(b0), "r"(b1))

// ======== conversion: fp32 -> MISMATCHED concat (R10, proven) ========
__global__ __launch_bounds__(256) void cvt_x_kernel(const float* __restrict__ src) {
    const size_t i = (size_t)blockIdx.x * 256 + threadIdx.x;
    const float4 v = ((const float4*)src)[i];
    const size_t e = i * 4;
    __nv_bfloat16* d = g_xc + (e >> 10) * K3 + (e & 1023);
    const float f[4] = { v.x, v.y, v.z, v.w };
    __nv_bfloat16 h[4], l[4];
#pragma unroll
    for (int j = 0; j < 4; j++) {
        h[j] = __float2bfloat16(f[j]);
        l[j] = __float2bfloat16(f[j] - __bfloat162float(h[j]));
    }
    *(__nv_bfloat162*)(d)        = __nv_bfloat162(h[0], h[1]);
    *(__nv_bfloat162*)(d + 2)    = __nv_bfloat162(h[2], h[3]);
    *(__nv_bfloat162*)(d + 1024) = __nv_bfloat162(h[0], h[1]);
    *(__nv_bfloat162*)(d + 1026) = __nv_bfloat162(h[2], h[3]);
    *(__nv_bfloat162*)(d + 2048) = __nv_bfloat162(l[0], l[1]);
    *(__nv_bfloat162*)(d + 2050) = __nv_bfloat162(l[2], l[3]);
}
__global__ __launch_bounds__(256) void cvt_w_kernel(const float* __restrict__ src) {
    const size_t i = (size_t)blockIdx.x * 256 + threadIdx.x;
    const float4 v = ((const float4*)src)[i];
    const size_t e = i * 4;
    __nv_bfloat16* d = g_wc + (e >> 10) * K3 + (e & 1023);
    const float f[4] = { v.x, v.y, v.z, v.w };
    __nv_bfloat16 h[4], l[4];
#pragma unroll
    for (int j = 0; j < 4; j++) {
        h[j] = __float2bfloat16(f[j]);
        l[j] = __float2bfloat16(f[j] - __bfloat162float(h[j]));
    }
    *(__nv_bfloat162*)(d)        = __nv_bfloat162(h[0], h[1]);
    *(__nv_bfloat162*)(d + 2)    = __nv_bfloat162(h[2], h[3]);
    *(__nv_bfloat162*)(d + 1024) = __nv_bfloat162(l[0], l[1]);
    *(__nv_bfloat162*)(d + 1026) = __nv_bfloat162(l[2], l[3]);
    *(__nv_bfloat162*)(d + 2048) = __nv_bfloat162(h[0], h[1]);
    *(__nv_bfloat162*)(d + 2050) = __nv_bfloat162(h[2], h[3]);
}

// ===================== Kernel 1: x_proj GEMM via mma.sync (R10, proven) ======
__global__ __launch_bounds__(256) void xproj_mma_kernel(
    const float* __restrict__ bih, const float* __restrict__ bhh)
{
    __shared__ __align__(16) char As[2 * 128 * 80];
    __shared__ __align__(16) char Bs[2 * 128 * 80];
    __shared__ float bias_sm[128];

    const int tid = threadIdx.x, wid = tid >> 5, lane = tid & 31;
    const int n0 = blockIdx.x * 128, m0 = blockIdx.y * 128;
    const int wm = wid & 3, wn = wid >> 2;
    const uint32_t suA = su32(As), suB = su32(Bs);
    const __nv_bfloat16* Xc = g_xc;
    const __nv_bfloat16* Wc = g_wc;

    if (tid < 128) bias_sm[tid] = bih[n0 + tid] + bhh[n0 + tid];

    float c[2][8][4];
#pragma unroll
    for (int mf = 0; mf < 2; mf++)
#pragma unroll
        for (int nf = 0; nf < 8; nf++)
#pragma unroll
            for (int q = 0; q < 4; q++) c[mf][nf][q] = 0.f;

    auto load_stage = [&](int kt, int buf) {
#pragma unroll
        for (int u = 0; u < 2; u++) {
            const int idx = tid + 256 * u;
            const int row = idx >> 2, c4 = idx & 3;
            CPA16(suA + buf * 10240 + row * 80 + c4 * 16,
                  Xc + (size_t)(m0 + row) * K3 + kt * 32 + c4 * 8);
            CPA16(suB + buf * 10240 + row * 80 + c4 * 16,
                  Wc + (size_t)(n0 + row) * K3 + kt * 32 + c4 * 8);
        }
    };

    load_stage(0, 0); CPA_COMMIT();
    load_stage(1, 1); CPA_COMMIT();

    const int lrow = lane & 15;
    const int lkof = (lane >> 4) << 4;

    const int NKT = K3 / 32;
    for (int kt = 0; kt < NKT; ++kt) {
        const int buf = kt & 1;
        CPA_WAIT1();
        __syncthreads();
        const uint32_t Ab = suA + buf * 10240;
        const uint32_t Bb = suB + buf * 10240;
#pragma unroll
        for (int s = 0; s < 2; s++) {
            const int kby = s * 32 + lkof;
            uint32_t a0[4], a1[4];
            LDSM4(a0, Ab + (wm * 32 + lrow) * 80 + kby);
            LDSM4(a1, Ab + (wm * 32 + 16 + lrow) * 80 + kby);
            uint32_t bf[4][4];
#pragma unroll
            for (int n4 = 0; n4 < 4; n4++)
                LDSM4(bf[n4], Bb + (wn * 64 + n4 * 16 + lrow) * 80 + kby);
#pragma unroll
            for (int n4 = 0; n4 < 4; n4++) {
                MMA16816(c[0][n4 * 2],     a0, bf[n4][0], bf[n4][2]);
                MMA16816(c[0][n4 * 2 + 1], a0, bf[n4][1], bf[n4][3]);
                MMA16816(c[1][n4 * 2],     a1, bf[n4][0], bf[n4][2]);
                MMA16816(c[1][n4 * 2 + 1], a1, bf[n4][1], bf[n4][3]);
            }
        }
        __syncthreads();
        if (kt + 2 < NKT) load_stage(kt + 2, buf);
        CPA_COMMIT();
    }

    const int rbase = m0 + wm * 32 + (lane >> 2);
    const int cloc = wn * 64 + (lane & 3) * 2;
#pragma unroll
    for (int mf = 0; mf < 2; mf++) {
#pragma unroll
        for (int nf = 0; nf < 8; nf++) {
            const int col = cloc + nf * 8;
            const float b0 = bias_sm[col], b1 = bias_sm[col + 1];
            float* p0 = g_xproj + (size_t)(rbase + mf * 16) * G4 + n0 + col;
            float* p1 = p0 + 8 * G4;
            *(float2*)p0 = make_float2(c[mf][nf][0] + b0, c[mf][nf][1] + b1);
            *(float2*)p1 = make_float2(c[mf][nf][2] + b0, c[mf][nf][3] + b1);
        }
    }
}

// ===================== grid barrier =====================
__device__ __forceinline__ void grid_barrier()
{
    __syncthreads();
    if (threadIdx.x == 0) {
        __threadfence();
        const unsigned gen = *(volatile unsigned*)&g_gen;
        atomicAdd(&g_count, 1u);
        if (blockIdx.x == 0) {
            while (*(volatile unsigned*)&g_count != gridDim.x) { __nanosleep(64); }
            g_count = 0;
            __threadfence();
            atomicAdd(&g_gen, 1u);
        } else {
            while (*(volatile unsigned*)&g_gen == gen) { __nanosleep(64); }
        }
        __threadfence();
    }
    __syncthreads();
}

// ===================== Kernel 2: tensor-core recurrence, warp-pair pipes =====
// 128 CTAs x 256 threads. W_hh hi/lo resident smem. Per-wm shared A buffers,
// 3-stage; pair {wm, wm+4}: wn=0 loads h_hi, wn=1 loads h_lo; one named
// bar.sync(wm+1, 64) per k-iter; NO __syncthreads in k-loop.
#define WROW 2064
#define SM_WH 0
#define SM_WL 66048
#define SM_A  132096               // 4 wm x 3 stages x 2560 (hi 1280 | lo 1280)
#define SM_C  162816               // 64 x 33 floats
#define SMT   171264

__global__ __launch_bounds__(256, 1) void lstm_rec_tc(
    const float* __restrict__ Whh, const float* __restrict__ h0,
    const float* __restrict__ c0, float* __restrict__ out, int out_size)
{
    extern __shared__ char sm[];
    const uint32_t smb = su32(sm);
    float* Csm = (float*)(sm + SM_C);

    const int tid = threadIdx.x, lane = tid & 31, wid = tid >> 5;
    const int j0 = blockIdx.x * 8;
    const int wm = wid & 3, wn = wid >> 2;
    const int lrow = lane & 15, lkof = (lane >> 4) << 4;
    const int lseg = (lane >> 4) * 32;
    const int b0_ = tid >> 3, jl = tid & 7;

    // ---- W_hh slice -> smem hi/lo (once) ----
    {
        const int n = tid >> 3, seg = tid & 7;
        const float* src = Whh + (size_t)((n >> 3) * HH + j0 + (n & 7)) * HH + seg * 128;
        __nv_bfloat16* dh = (__nv_bfloat16*)(sm + SM_WH + n * WROW) + seg * 128;
        __nv_bfloat16* dl = (__nv_bfloat16*)(sm + SM_WL + n * WROW) + seg * 128;
        for (int q = 0; q < 32; q++) {
            const float4 v = *(const float4*)&src[q * 4];
            const float f[4] = { v.x, v.y, v.z, v.w };
            __nv_bfloat16 h4[4], l4[4];
#pragma unroll
            for (int j = 0; j < 4; j++) {
                h4[j] = __float2bfloat16(f[j]);
                l4[j] = __float2bfloat16(f[j] - __bfloat162float(h4[j]));
            }
            *(__nv_bfloat162*)(dh + q * 4)     = __nv_bfloat162(h4[0], h4[1]);
            *(__nv_bfloat162*)(dh + q * 4 + 2) = __nv_bfloat162(h4[2], h4[3]);
            *(__nv_bfloat162*)(dl + q * 4)     = __nv_bfloat162(l4[0], l4[1]);
            *(__nv_bfloat162*)(dl + q * 4 + 2) = __nv_bfloat162(l4[2], l4[3]);
        }
    }
    // ---- h0 split -> g_hh[0] ----
    {
        const size_t e = ((size_t)blockIdx.x * 256 + tid) * 2;
        const float2 v = *(const float2*)&h0[e];
        const __nv_bfloat16 h0a = __float2bfloat16(v.x);
        const __nv_bfloat16 h0b = __float2bfloat16(v.y);
        *(__nv_bfloat162*)&g_hh[0][0][e] = __nv_bfloat162(h0a, h0b);
        *(__nv_bfloat162*)&g_hh[0][1][e] = __nv_bfloat162(
            __float2bfloat16(v.x - __bfloat162float(h0a)),
            __float2bfloat16(v.y - __bfloat162float(h0b)));
    }
    float c_reg[2], hlast[2] = {0.f, 0.f};
    c_reg[0] = c0[(size_t)b0_ * HH + j0 + jl];
    c_reg[1] = c0[(size_t)(b0_ + 32) * HH + j0 + jl];

    grid_barrier();

    const int hT = TS * BB * HH;
    const uint32_t abase = smb + SM_A + wm * 7680 + wn * 1280 + lrow * 80 + lseg;
    const uint32_t cbase = smb + SM_A + wm * 7680 + lrow * 80;
    const uint32_t Bhr = smb + SM_WH + (wn * 16 + lrow) * WROW;
    const uint32_t Blr = smb + SM_WL + (wn * 16 + lrow) * WROW;

    for (int t = 0; t < TS; ++t) {
        const int rb = t % 3, wb = (t + 1) % 3;
        const char* Asrc = (const char*)g_hh[rb][wn];   // wn0: hi, wn1: lo
        const size_t sof = (size_t)(wm * 16 + lrow) * 2048 + lseg;

        // xp prefetch (consumed in epilogue)
        float xpv[2][4];
        {
            const float* xpt = g_xproj + (size_t)t * BB * G4;
#pragma unroll
            for (int q = 0; q < 2; q++)
#pragma unroll
                for (int g = 0; g < 4; g++)
                    xpv[q][g] = __ldcs(&xpt[(size_t)(b0_ + 32 * q) * G4 + g * HH + j0 + jl]);
        }

        float c[6][4];
#pragma unroll
        for (int i = 0; i < 6; i++)
#pragma unroll
            for (int q = 0; q < 4; q++) c[i][q] = 0.f;

        // prologue: stages 0, 1
        {
            const char* s0 = Asrc + sof;
            CPA16(abase, s0); CPA16(abase + 16, s0 + 16); CPA_COMMIT();
            const char* s1 = Asrc + sof + 64;
            CPA16(abase + 2560, s1); CPA16(abase + 2560 + 16, s1 + 16); CPA_COMMIT();
        }

        for (int kt = 0; kt < 32; ++kt) {
            CPA_WAIT1();
            asm volatile("bar.sync %0, 64;" :: "r"(wm + 1) : "memory");
            // safe to refill buf (kt+2)%3 == (kt-1)%3: pair finished kt-1
            if (kt + 2 < 32) {
                const uint32_t d = abase + ((kt + 2) % 3) * 2560;
                const char* s = Asrc + sof + (size_t)(kt + 2) * 64;
                CPA16(d, s); CPA16(d + 16, s + 16);
            }
            CPA_COMMIT();

            const uint32_t Ahs = cbase + (kt % 3) * 2560;
            const uint32_t Als = Ahs + 1280;
#pragma unroll
            for (int s = 0; s < 2; s++) {
                const int kby = s * 32 + lkof;
                const int kwb = kt * 64 + kby;
                uint32_t ah[4], al[4], bh[4], bl[4];
                LDSM4(ah, Ahs + kby);
                LDSM4(al, Als + kby);
                LDSM4(bh, Bhr + kwb);
                LDSM4(bl, Blr + kwb);
                MMA16816(c[0], ah, bh[0], bh[2]);
                MMA16816(c[1], ah, bh[1], bh[3]);
                MMA16816(c[2], ah, bl[0], bl[2]);
                MMA16816(c[3], ah, bl[1], bl[3]);
                MMA16816(c[4], al, bh[0], bh[2]);
                MMA16816(c[5], al, bh[1], bh[3]);
            }
        }

        // ---- merge streams, fragments -> Csm ----
        {
            const int r0 = wm * 16 + (lane >> 2);
            const int cb = wn * 16 + (lane & 3) * 2;
#pragma unroll
            for (int nf = 0; nf < 2; nf++) {
                Csm[r0 * 33 + cb + nf * 8]           = c[nf][0] + c[nf + 2][0] + c[nf + 4][0];
                Csm[r0 * 33 + cb + nf * 8 + 1]       = c[nf][1] + c[nf + 2][1] + c[nf + 4][1];
                Csm[(r0 + 8) * 33 + cb + nf * 8]     = c[nf][2] + c[nf + 2][2] + c[nf + 4][2];
                Csm[(r0 + 8) * 33 + cb + nf * 8 + 1] = c[nf][3] + c[nf + 2][3] + c[nf + 4][3];
            }
        }
        __syncthreads();

        // ---- LSTM cell (fp32, c in registers) ----
#pragma unroll
        for (int q = 0; q < 2; q++) {
            const int b = b0_ + 32 * q;
            const float Gi = Csm[b * 33 + jl]      + xpv[q][0];
            const float Gf = Csm[b * 33 + 8 + jl]  + xpv[q][1];
            const float Gg = Csm[b * 33 + 16 + jl] + xpv[q][2];
            const float Go = Csm[b * 33 + 24 + jl] + xpv[q][3];
            const float iv = sigf(Gi), fv = sigf(Gf);
            const float gv = tanhf(Gg), ov = sigf(Go);
            const float cn = fmaf(fv, c_reg[q], iv * gv);
            c_reg[q] = cn;
            const float hv = ov * tanhf(cn);
            hlast[q] = hv;
            out[((size_t)t * BB + b) * HH + j0 + jl] = hv;
            const __nv_bfloat16 hh = __float2bfloat16(hv);
            g_hh[wb][0][b * HH + j0 + jl] = hh;
            g_hh[wb][1][b * HH + j0 + jl] =
                __float2bfloat16(hv - __bfloat162float(hh));
        }
        grid_barrier();
    }

    if (out_size >= hT + 2 * BB * HH) {
#pragma unroll
        for (int q = 0; q < 2; q++) {
            const int b = b0_ + 32 * q;
            out[hT + (size_t)b * HH + j0 + jl] = hlast[q];
            out[hT + BB * HH + (size_t)b * HH + j0 + jl] = c_reg[q];
        }
    }
}

extern "C" void kernel_launch(void* const* d_in, const int* in_sizes, int n_in,
                              void* d_out, int out_size)
{
    const float* x   = (const float*)d_in[0];
    const float* Wih = (const float*)d_in[1];
    const float* Whh = (const float*)d_in[2];
    const float* bih = (const float*)d_in[3];
    const float* bhh = (const float*)d_in[4];
    const float* h0  = (const float*)d_in[5];
    const float* c0  = (const float*)d_in[6];
    float* out = (float*)d_out;

    static bool attr_set = false;
    if (!attr_set) {
        cudaFuncSetAttribute(lstm_rec_tc,
                             cudaFuncAttributeMaxDynamicSharedMemorySize, SMT);
        attr_set = true;
    }

    cvt_x_kernel<<<(TS * BB * HH / 4) / 256, 256>>>(x);
    cvt_w_kernel<<<(G4 * HH / 4) / 256, 256>>>(Wih);
    dim3 g1(G4 / 128, (TS * BB) / 128);
    xproj_mma_kernel<<<g1, 256>>>(bih, bhh);
    lstm_rec_tc<<<128, 256, SMT>>>(Whh, h0, c0, out, out_size);
}

// round 14
// speedup vs baseline: 2.5286x; 1.1191x over previous
#include <cuda_runtime.h>
#include <cuda_bf16.h>
#include <cstdint>
#include <cstddef>

#define TS 1024
#define BB 64
#define HH 1024
#define G4 4096
#define K3 3072

__device__ float g_xproj[(size_t)TS * BB * G4];
__device__ unsigned g_count = 0;
__device__ unsigned g_gen = 0;
__device__ __align__(256) __nv_bfloat16 g_xc[(size_t)TS * BB * K3];  // [row][hi|hi|lo]
__device__ __align__(256) __nv_bfloat16 g_wc[(size_t)G4 * K3];       // [row][hi|lo|hi]
__device__ __align__(256) __nv_bfloat16 g_hh[3][2][BB * HH];         // [buf][hi/lo][b*HH+j]

__device__ __forceinline__ float sigf(float x) { return 1.0f / (1.0f + __expf(-x)); }

__device__ __forceinline__ uint32_t su32(const void* p) {
    uint32_t a;
    asm("{ .reg .u64 t; cvta.to.shared.u64 t, %1; cvt.u32.u64 %0, t; }" : "=r"(a) : "l"(p));
    return a;
}

#define CPA16(dst, src) asm volatile("cp.async.cg.shared.global [%0], [%1], 16;" :: "r"(dst), "l"(src))
#define CPA_COMMIT() asm volatile("cp.async.commit_group;" ::: "memory")
#define CPA_WAIT1() asm volatile("cp.async.wait_group 1;" ::: "memory")

#define LDSM4(r, addr) asm volatile( \
    "ldmatrix.sync.aligned.m8n8.x4.shared.b16 {%0,%1,%2,%3}, [%4];" \
    : "=r"((r)[0]), "=r"((r)[1]), "=r"((r)[2]), "=r"((r)[3]) : "r"(addr))

#define MMA16816(d, a, b0, b1) asm volatile( \
    "mma.sync.aligned.m16n8k16.row.col.f32.bf16.bf16.f32 " \
    "{%0,%1,%2,%3}, {%4,%5,%6,%7}, {%8,%9}, {%0,%1,%2,%3};" \
    : "+f"((d)[0]), "+f"((d)[1]), "+f"((d)[2]), "+f"((d)[3]) \
    : "r"((a)[0]), "r"((a)[1]), "r"((a)[2]), "r"((a)[3]), "r"(b0), "r"(b1))

// ======== conversion: fp32 -> MISMATCHED concat (R10, proven) ========
__global__ __launch_bounds__(256) void cvt_x_kernel(const float* __restrict__ src) {
    const size_t i = (size_t)blockIdx.x * 256 + threadIdx.x;
    const float4 v = ((const float4*)src)[i];
    const size_t e = i * 4;
    __nv_bfloat16* d = g_xc + (e >> 10) * K3 + (e & 1023);
    const float f[4] = { v.x, v.y, v.z, v.w };
    __nv_bfloat16 h[4], l[4];
#pragma unroll
    for (int j = 0; j < 4; j++) {
        h[j] = __float2bfloat16(f[j]);
        l[j] = __float2bfloat16(f[j] - __bfloat162float(h[j]));
    }
    *(__nv_bfloat162*)(d)        = __nv_bfloat162(h[0], h[1]);
    *(__nv_bfloat162*)(d + 2)    = __nv_bfloat162(h[2], h[3]);
    *(__nv_bfloat162*)(d + 1024) = __nv_bfloat162(h[0], h[1]);
    *(__nv_bfloat162*)(d + 1026) = __nv_bfloat162(h[2], h[3]);
    *(__nv_bfloat162*)(d + 2048) = __nv_bfloat162(l[0], l[1]);
    *(__nv_bfloat162*)(d + 2050) = __nv_bfloat162(l[2], l[3]);
}
__global__ __launch_bounds__(256) void cvt_w_kernel(const float* __restrict__ src) {
    const size_t i = (size_t)blockIdx.x * 256 + threadIdx.x;
    const float4 v = ((const float4*)src)[i];
    const size_t e = i * 4;
    __nv_bfloat16* d = g_wc + (e >> 10) * K3 + (e & 1023);
    const float f[4] = { v.x, v.y, v.z, v.w };
    __nv_bfloat16 h[4], l[4];
#pragma unroll
    for (int j = 0; j < 4; j++) {
        h[j] = __float2bfloat16(f[j]);
        l[j] = __float2bfloat16(f[j] - __bfloat162float(h[j]));
    }
    *(__nv_bfloat162*)(d)        = __nv_bfloat162(h[0], h[1]);
    *(__nv_bfloat162*)(d + 2)    = __nv_bfloat162(h[2], h[3]);
    *(__nv_bfloat162*)(d + 1024) = __nv_bfloat162(l[0], l[1]);
    *(__nv_bfloat162*)(d + 1026) = __nv_bfloat162(l[2], l[3]);
    *(__nv_bfloat162*)(d + 2048) = __nv_bfloat162(h[0], h[1]);
    *(__nv_bfloat162*)(d + 2050) = __nv_bfloat162(h[2], h[3]);
}

// ===================== Kernel 1: x_proj GEMM via mma.sync (R10, proven) ======
__global__ __launch_bounds__(256) void xproj_mma_kernel(
    const float* __restrict__ bih, const float* __restrict__ bhh)
{
    __shared__ __align__(16) char As[2 * 128 * 80];
    __shared__ __align__(16) char Bs[2 * 128 * 80];
    __shared__ float bias_sm[128];

    const int tid = threadIdx.x, wid = tid >> 5, lane = tid & 31;
    const int n0 = blockIdx.x * 128, m0 = blockIdx.y * 128;
    const int wm = wid & 3, wn = wid >> 2;
    const uint32_t suA = su32(As), suB = su32(Bs);
    const __nv_bfloat16* Xc = g_xc;
    const __nv_bfloat16* Wc = g_wc;

    if (tid < 128) bias_sm[tid] = bih[n0 + tid] + bhh[n0 + tid];

    float c[2][8][4];
#pragma unroll
    for (int mf = 0; mf < 2; mf++)
#pragma unroll
        for (int nf = 0; nf < 8; nf++)
#pragma unroll
            for (int q = 0; q < 4; q++) c[mf][nf][q] = 0.f;

    auto load_stage = [&](int kt, int buf) {
#pragma unroll
        for (int u = 0; u < 2; u++) {
            const int idx = tid + 256 * u;
            const int row = idx >> 2, c4 = idx & 3;
            CPA16(suA + buf * 10240 + row * 80 + c4 * 16,
                  Xc + (size_t)(m0 + row) * K3 + kt * 32 + c4 * 8);
            CPA16(suB + buf * 10240 + row * 80 + c4 * 16,
                  Wc + (size_t)(n0 + row) * K3 + kt * 32 + c4 * 8);
        }
    };

    load_stage(0, 0); CPA_COMMIT();
    load_stage(1, 1); CPA_COMMIT();

    const int lrow = lane & 15;
    const int lkof = (lane >> 4) << 4;

    const int NKT = K3 / 32;
    for (int kt = 0; kt < NKT; ++kt) {
        const int buf = kt & 1;
        CPA_WAIT1();
        __syncthreads();
        const uint32_t Ab = suA + buf * 10240;
        const uint32_t Bb = suB + buf * 10240;
#pragma unroll
        for (int s = 0; s < 2; s++) {
            const int kby = s * 32 + lkof;
            uint32_t a0[4], a1[4];
            LDSM4(a0, Ab + (wm * 32 + lrow) * 80 + kby);
            LDSM4(a1, Ab + (wm * 32 + 16 + lrow) * 80 + kby);
            uint32_t bf[4][4];
#pragma unroll
            for (int n4 = 0; n4 < 4; n4++)
                LDSM4(bf[n4], Bb + (wn * 64 + n4 * 16 + lrow) * 80 + kby);
#pragma unroll
            for (int n4 = 0; n4 < 4; n4++) {
                MMA16816(c[0][n4 * 2],     a0, bf[n4][0], bf[n4][2]);
                MMA16816(c[0][n4 * 2 + 1], a0, bf[n4][1], bf[n4][3]);
                MMA16816(c[1][n4 * 2],     a1, bf[n4][0], bf[n4][2]);
                MMA16816(c[1][n4 * 2 + 1], a1, bf[n4][1], bf[n4][3]);
            }
        }
        __syncthreads();
        if (kt + 2 < NKT) load_stage(kt + 2, buf);
        CPA_COMMIT();
    }

    const int rbase = m0 + wm * 32 + (lane >> 2);
    const int cloc = wn * 64 + (lane & 3) * 2;
#pragma unroll
    for (int mf = 0; mf < 2; mf++) {
#pragma unroll
        for (int nf = 0; nf < 8; nf++) {
            const int col = cloc + nf * 8;
            const float b0 = bias_sm[col], b1 = bias_sm[col + 1];
            float* p0 = g_xproj + (size_t)(rbase + mf * 16) * G4 + n0 + col;
            float* p1 = p0 + 8 * G4;
            *(float2*)p0 = make_float2(c[mf][nf][0] + b0, c[mf][nf][1] + b1);
            *(float2*)p1 = make_float2(c[mf][nf][2] + b0, c[mf][nf][3] + b1);
        }
    }
}

// ===================== grid barrier =====================
__device__ __forceinline__ void grid_barrier()
{
    __syncthreads();
    if (threadIdx.x == 0) {
        __threadfence();
        const unsigned gen = *(volatile unsigned*)&g_gen;
        atomicAdd(&g_count, 1u);
        if (blockIdx.x == 0) {
            while (*(volatile unsigned*)&g_count != gridDim.x) { __nanosleep(64); }
            g_count = 0;
            __threadfence();
            atomicAdd(&g_gen, 1u);
        } else {
            while (*(volatile unsigned*)&g_gen == gen) { __nanosleep(64); }
        }
        __threadfence();
    }
    __syncthreads();
}

// ===================== Kernel 2: tensor-core recurrence, K-split 16 warps ====
// 128 CTAs x 512 threads. Warp (km, wm, wn): km = k-half (512 elems, 16 iters),
// wm = row group (16 rows), wn = col half (16 cols) AND A-type loader (hi/lo).
// Pair {wn0, wn1} shares A buffers; named bar.sync(1+km*4+wm, 64) per iter.
// Two partial C regions (km 0/1) summed in cell phase.
#define WROW 2064
#define SM_WH 0
#define SM_WL 66048
#define SM_A  132096               // 8 groups x 3 stages x 2560
#define SM_C  193536               // 2 x 64 x 33 floats
#define SMT   210432

__global__ __launch_bounds__(512, 1) void lstm_rec_tc(
    const float* __restrict__ Whh, const float* __restrict__ h0,
    const float* __restrict__ c0, float* __restrict__ out, int out_size)
{
    extern __shared__ char sm[];
    const uint32_t smb = su32(sm);

    const int tid = threadIdx.x, lane = tid & 31, wid = tid >> 5;
    const int j0 = blockIdx.x * 8;
    const int km = wid >> 3;
    const int wm = wid & 3, wn = (wid >> 2) & 1;
    const int grp8 = km * 4 + wm;
    const int lrow = lane & 15, lkof = (lane >> 4) << 4;
    const int lseg = (lane >> 4) * 32;
    const int b0_ = tid >> 3, jl = tid & 7;   // one (batch, col) per thread

    // ---- W_hh slice -> smem hi/lo (once): 32 rows x 1024 ----
    {
        const int n = tid >> 4, seg = tid & 15;
        const float* src = Whh + (size_t)((n >> 3) * HH + j0 + (n & 7)) * HH + seg * 64;
        __nv_bfloat16* dh = (__nv_bfloat16*)(sm + SM_WH + n * WROW) + seg * 64;
        __nv_bfloat16* dl = (__nv_bfloat16*)(sm + SM_WL + n * WROW) + seg * 64;
        for (int q = 0; q < 16; q++) {
            const float4 v = *(const float4*)&src[q * 4];
            const float f[4] = { v.x, v.y, v.z, v.w };
            __nv_bfloat16 h4[4], l4[4];
#pragma unroll
            for (int j = 0; j < 4; j++) {
                h4[j] = __float2bfloat16(f[j]);
                l4[j] = __float2bfloat16(f[j] - __bfloat162float(h4[j]));
            }
            *(__nv_bfloat162*)(dh + q * 4)     = __nv_bfloat162(h4[0], h4[1]);
            *(__nv_bfloat162*)(dh + q * 4 + 2) = __nv_bfloat162(h4[2], h4[3]);
            *(__nv_bfloat162*)(dl + q * 4)     = __nv_bfloat162(l4[0], l4[1]);
            *(__nv_bfloat162*)(dl + q * 4 + 2) = __nv_bfloat162(l4[2], l4[3]);
        }
    }
    // ---- h0 split -> g_hh[0] (one elem/thread) ----
    {
        const size_t e = (size_t)blockIdx.x * 512 + tid;
        const float v = h0[e];
        const __nv_bfloat16 hh = __float2bfloat16(v);
        g_hh[0][0][e] = hh;
        g_hh[0][1][e] = __float2bfloat16(v - __bfloat162float(hh));
    }
    float c_reg = c0[(size_t)b0_ * HH + j0 + jl];
    float hlast = 0.f;

    grid_barrier();

    const int hT = TS * BB * HH;
    const uint32_t abase = smb + SM_A + grp8 * 7680 + wn * 1280 + lrow * 80 + lseg;
    const uint32_t cbase = smb + SM_A + grp8 * 7680 + lrow * 80;
    const uint32_t Bhr = smb + SM_WH + (wn * 16 + lrow) * WROW + km * 1024;
    const uint32_t Blr = smb + SM_WL + (wn * 16 + lrow) * WROW + km * 1024;
    float* Csm0 = (float*)(sm + SM_C);
    float* Csm1 = Csm0 + 64 * 33;
    float* Cmine = km ? Csm1 : Csm0;

    for (int t = 0; t < TS; ++t) {
        const int rb = t % 3, wb = (t + 1) % 3;
        const char* Asrc = (const char*)g_hh[rb][wn];   // wn0: hi, wn1: lo
        const size_t sof = (size_t)(wm * 16 + lrow) * 2048 + km * 1024 + lseg;

        // xp prefetch (one (b, jl) per thread)
        float xpv[4];
        {
            const float* xpr = g_xproj + ((size_t)t * BB + b0_) * G4;
#pragma unroll
            for (int g = 0; g < 4; g++)
                xpv[g] = __ldcs(&xpr[g * HH + j0 + jl]);
        }

        float c[6][4];
#pragma unroll
        for (int i = 0; i < 6; i++)
#pragma unroll
            for (int q = 0; q < 4; q++) c[i][q] = 0.f;

        // prologue: stages 0, 1
        {
            const char* s0 = Asrc + sof;
            CPA16(abase, s0); CPA16(abase + 16, s0 + 16); CPA_COMMIT();
            const char* s1 = Asrc + sof + 64;
            CPA16(abase + 2560, s1); CPA16(abase + 2560 + 16, s1 + 16); CPA_COMMIT();
        }

        for (int kt = 0; kt < 16; ++kt) {
            CPA_WAIT1();
            asm volatile("bar.sync %0, 64;" :: "r"(1 + grp8) : "memory");
            if (kt + 2 < 16) {
                const uint32_t d = abase + ((kt + 2) % 3) * 2560;
                const char* s = Asrc + sof + (size_t)(kt + 2) * 64;
                CPA16(d, s); CPA16(d + 16, s + 16);
            }
            CPA_COMMIT();

            const uint32_t Ahs = cbase + (kt % 3) * 2560;
            const uint32_t Als = Ahs + 1280;
#pragma unroll
            for (int s = 0; s < 2; s++) {
                const int kby = s * 32 + lkof;
                const int kwb = kt * 64 + kby;
                uint32_t ah[4], al[4], bh[4], bl[4];
                LDSM4(ah, Ahs + kby);
                LDSM4(al, Als + kby);
                LDSM4(bh, Bhr + kwb);
                LDSM4(bl, Blr + kwb);
                MMA16816(c[0], ah, bh[0], bh[2]);
                MMA16816(c[1], ah, bh[1], bh[3]);
                MMA16816(c[2], ah, bl[0], bl[2]);
                MMA16816(c[3], ah, bl[1], bl[3]);
                MMA16816(c[4], al, bh[0], bh[2]);
                MMA16816(c[5], al, bh[1], bh[3]);
            }
        }

        // ---- merge streams, fragments -> C region for this km ----
        {
            const int r0 = wm * 16 + (lane >> 2);
            const int cb = wn * 16 + (lane & 3) * 2;
#pragma unroll
            for (int nf = 0; nf < 2; nf++) {
                Cmine[r0 * 33 + cb + nf * 8]           = c[nf][0] + c[nf + 2][0] + c[nf + 4][0];
                Cmine[r0 * 33 + cb + nf * 8 + 1]       = c[nf][1] + c[nf + 2][1] + c[nf + 4][1];
                Cmine[(r0 + 8) * 33 + cb + nf * 8]     = c[nf][2] + c[nf + 2][2] + c[nf + 4][2];
                Cmine[(r0 + 8) * 33 + cb + nf * 8 + 1] = c[nf][3] + c[nf + 2][3] + c[nf + 4][3];
            }
        }
        __syncthreads();

        // ---- LSTM cell: one (b, jl) per thread, sum km halves ----
        {
            const int b = b0_;
            const float Gi = Csm0[b * 33 + jl]      + Csm1[b * 33 + jl]      + xpv[0];
            const float Gf = Csm0[b * 33 + 8 + jl]  + Csm1[b * 33 + 8 + jl]  + xpv[1];
            const float Gg = Csm0[b * 33 + 16 + jl] + Csm1[b * 33 + 16 + jl] + xpv[2];
            const float Go = Csm0[b * 33 + 24 + jl] + Csm1[b * 33 + 24 + jl] + xpv[3];
            const float iv = sigf(Gi), fv = sigf(Gf);
            const float gv = tanhf(Gg), ov = sigf(Go);
            const float cn = fmaf(fv, c_reg, iv * gv);
            c_reg = cn;
            const float hv = ov * tanhf(cn);
            hlast = hv;
            out[((size_t)t * BB + b) * HH + j0 + jl] = hv;
            const __nv_bfloat16 hh = __float2bfloat16(hv);
            g_hh[wb][0][b * HH + j0 + jl] = hh;
            g_hh[wb][1][b * HH + j0 + jl] =
                __float2bfloat16(hv - __bfloat162float(hh));
        }
        grid_barrier();
    }

    if (out_size >= hT + 2 * BB * HH) {
        out[hT + (size_t)b0_ * HH + j0 + jl] = hlast;
        out[hT + BB * HH + (size_t)b0_ * HH + j0 + jl] = c_reg;
    }
}

extern "C" void kernel_launch(void* const* d_in, const int* in_sizes, int n_in,
                              void* d_out, int out_size)
{
    const float* x   = (const float*)d_in[0];
    const float* Wih = (const float*)d_in[1];
    const float* Whh = (const float*)d_in[2];
    const float* bih = (const float*)d_in[3];
    const float* bhh = (const float*)d_in[4];
    const float* h0  = (const float*)d_in[5];
    const float* c0  = (const float*)d_in[6];
    float* out = (float*)d_out;

    static bool attr_set = false;
    if (!attr_set) {
        cudaFuncSetAttribute(lstm_rec_tc,
                             cudaFuncAttributeMaxDynamicSharedMemorySize, SMT);
        attr_set = true;
    }

    cvt_x_kernel<<<(TS * BB * HH / 4) / 256, 256>>>(x);
    cvt_w_kernel<<<(G4 * HH / 4) / 256, 256>>>(Wih);
    dim3 g1(G4 / 128, (TS * BB) / 128);
    xproj_mma_kernel<<<g1, 256>>>(bih, bhh);
    lstm_rec_tc<<<128, 512, SMT>>>(Whh, h0, c0, out, out_size);
}